// round 2
// baseline (speedup 1.0000x reference)
#include <cuda_runtime.h>
#include <math.h>

// Problem constants
#define BROWS 16384
#define IDIM  512
#define HDIM  512
#define KDIM1 1024   // I + H
#define NDIM1 2048   // 4*H
#define LN_EPS 1e-5f

// Scratch (device globals: allocation-free rule)
__device__ float g_act[(size_t)BROWS * NDIM1];  // activated gates [B, 4H]  (128 MB)
__device__ float g_s  [(size_t)BROWS * HDIM];   // o * tanh(cell) [B, H]    (32 MB)

__device__ __forceinline__ float sigmoidf_(float x) { return 1.0f / (1.0f + expf(-x)); }

// ---------------------------------------------------------------------------
// Tiled SGEMM: C[M,N] = A[M,K] @ Bmat^T (+bias, +activation)
// Bmat is row-major [N, K] (torch Linear weight layout).
// MODE 0: A = concat(x, h_prev) [B, 1024]; Bmat = W [2048,1024]; bias=b;
//         epilogue: sigmoid/tanh per gate; writes g_act.
// MODE 1: A = g_s [B, 512]; Bmat = Wp [512,512]; no bias/act; writes C ptr.
// Tile: BM=BN=128, BK=16, 256 threads, 8x8 per thread.
// ---------------------------------------------------------------------------
template <int MODE>
__global__ __launch_bounds__(256)
void sgemm_kernel(const float* __restrict__ x,
                  const float* __restrict__ h_prev,
                  const float* __restrict__ Bmat,
                  const float* __restrict__ bias,
                  float* __restrict__ Cout,
                  int K)
{
    __shared__ float As[16][128];
    __shared__ float Bs[16][128];

    const int tid = threadIdx.x;
    const int bm  = blockIdx.y * 128;
    const int bn  = blockIdx.x * 128;

    const int tx = tid & 15;   // 0..15  (column group)
    const int ty = tid >> 4;   // 0..15  (row group)

    float acc[8][8];
#pragma unroll
    for (int i = 0; i < 8; i++)
#pragma unroll
        for (int j = 0; j < 8; j++) acc[i][j] = 0.0f;

    for (int bk = 0; bk < K; bk += 16) {
        // --- load A tile (128 rows x 16 cols), store transposed As[k][m] ---
#pragma unroll
        for (int it = 0; it < 2; it++) {
            int l  = tid + it * 256;      // 0..511
            int r  = l >> 2;              // row within tile 0..127
            int c4 = (l & 3) << 2;        // 0,4,8,12
            int grow = bm + r;
            int gcol = bk + c4;
            float4 va;
            if (MODE == 0) {
                if (gcol < IDIM)
                    va = *reinterpret_cast<const float4*>(x + (size_t)grow * IDIM + gcol);
                else
                    va = *reinterpret_cast<const float4*>(h_prev + (size_t)grow * HDIM + (gcol - IDIM));
            } else {
                va = *reinterpret_cast<const float4*>(g_s + (size_t)grow * HDIM + gcol);
            }
            As[c4 + 0][r] = va.x; As[c4 + 1][r] = va.y;
            As[c4 + 2][r] = va.z; As[c4 + 3][r] = va.w;
        }
        // --- load B tile: Bs[k][n] = Bmat[bn+n][bk+k] ---
#pragma unroll
        for (int it = 0; it < 2; it++) {
            int l  = tid + it * 256;
            int r  = l >> 2;              // n within tile
            int c4 = (l & 3) << 2;        // k within tile
            float4 vb = *reinterpret_cast<const float4*>(Bmat + (size_t)(bn + r) * K + bk + c4);
            Bs[c4 + 0][r] = vb.x; Bs[c4 + 1][r] = vb.y;
            Bs[c4 + 2][r] = vb.z; Bs[c4 + 3][r] = vb.w;
        }
        __syncthreads();

#pragma unroll
        for (int kk = 0; kk < 16; kk++) {
            float ra[8], rb[8];
#pragma unroll
            for (int i = 0; i < 8; i++) ra[i] = As[kk][ty * 8 + i];
#pragma unroll
            for (int j = 0; j < 8; j++) rb[j] = Bs[kk][tx * 8 + j];
#pragma unroll
            for (int i = 0; i < 8; i++)
#pragma unroll
                for (int j = 0; j < 8; j++) acc[i][j] += ra[i] * rb[j];
        }
        __syncthreads();
    }

    // --- epilogue ---
#pragma unroll
    for (int i = 0; i < 8; i++) {
        int grow = bm + ty * 8 + i;
#pragma unroll
        for (int j = 0; j < 8; j++) {
            int gcol = bn + tx * 8 + j;
            float v = acc[i][j];
            if (MODE == 0) {
                v += bias[gcol];
                int gate = gcol >> 9;           // 0:i 1:f 2:g 3:o
                v = (gate == 2) ? tanhf(v) : sigmoidf_(v);
                g_act[(size_t)grow * NDIM1 + gcol] = v;
            } else {
                Cout[(size_t)grow * HDIM + gcol] = v;
            }
        }
    }
}

// ---------------------------------------------------------------------------
// LayerNorm + cell + s = o*tanh(cell). One block (512 threads) per row.
// Writes cell into out_cell (= d_out + B*H), writes s into g_s.
// ---------------------------------------------------------------------------
__global__ __launch_bounds__(512)
void ln_kernel(const float* __restrict__ c_prev,
               const float* __restrict__ gamma,
               const float* __restrict__ beta,
               float* __restrict__ out_cell)
{
    const int b = blockIdx.x;
    const int h = threadIdx.x;
    const float* row = g_act + (size_t)b * NDIM1;

    float ig = row[h];            // sigmoid(i)
    float fg = row[HDIM + h];     // sigmoid(f)
    float gg = row[2 * HDIM + h]; // tanh(g)
    float og = row[3 * HDIM + h]; // sigmoid(o)

    float c = fg * c_prev[(size_t)b * HDIM + h] + ig * gg;

    __shared__ float s_sum[512];
    __shared__ float s_sq[512];
    s_sum[h] = c;
    s_sq[h]  = c * c;
    __syncthreads();
#pragma unroll
    for (int ofs = 256; ofs > 0; ofs >>= 1) {
        if (h < ofs) {
            s_sum[h] += s_sum[h + ofs];
            s_sq[h]  += s_sq[h + ofs];
        }
        __syncthreads();
    }
    float mu  = s_sum[0] * (1.0f / HDIM);
    float var = s_sq[0] * (1.0f / HDIM) - mu * mu;
    float inv = rsqrtf(var + LN_EPS);

    float cn = (c - mu) * inv * gamma[h] + beta[h];
    out_cell[(size_t)b * HDIM + h] = cn;
    g_s[(size_t)b * HDIM + h] = og * tanhf(cn);
}

// ---------------------------------------------------------------------------
extern "C" void kernel_launch(void* const* d_in, const int* in_sizes, int n_in,
                              void* d_out, int out_size)
{
    const float* x      = (const float*)d_in[0];
    const float* h_prev = (const float*)d_in[1];
    const float* c_prev = (const float*)d_in[2];
    const float* W      = (const float*)d_in[3];
    const float* b      = (const float*)d_in[4];
    const float* gamma  = (const float*)d_in[5];
    const float* beta   = (const float*)d_in[6];
    const float* Wp     = (const float*)d_in[7];
    float* out = (float*)d_out;                       // [out | cell]
    float* out_cell = out + (size_t)BROWS * HDIM;

    // GEMM1: gates (+bias, +activation) -> g_act
    dim3 grid1(NDIM1 / 128, BROWS / 128);             // (16, 128)
    sgemm_kernel<0><<<grid1, 256>>>(x, h_prev, W, b, nullptr, KDIM1);

    // LayerNorm + cell + s
    ln_kernel<<<BROWS, 512>>>(c_prev, gamma, beta, out_cell);

    // GEMM2: out = s @ Wp^T
    dim3 grid2(HDIM / 128, BROWS / 128);              // (4, 128)
    sgemm_kernel<1><<<grid2, 256>>>(nullptr, nullptr, Wp, nullptr, out, HDIM);
}

// round 5
// speedup vs baseline: 2.4049x; 2.4049x over previous
#include <cuda_runtime.h>
#include <cuda_bf16.h>
#include <math.h>
#include <stdint.h>

#define BROWS 16384
#define HDIM  512
#define KDIM1 1024   // I + H
#define NDIM1 2048   // 4*H
#define LN_EPS 1e-5f

// ---------------- scratch (device globals; allocation-free rule) -----------
__device__ float g_act[(size_t)BROWS * NDIM1];              // activated gates
__device__ __nv_bfloat16 g_Ahi[(size_t)BROWS * KDIM1];
__device__ __nv_bfloat16 g_Alo[(size_t)BROWS * KDIM1];
__device__ __nv_bfloat16 g_Whi[(size_t)NDIM1 * KDIM1];
__device__ __nv_bfloat16 g_Wlo[(size_t)NDIM1 * KDIM1];
__device__ __nv_bfloat16 g_Shi[(size_t)BROWS * HDIM];
__device__ __nv_bfloat16 g_Slo[(size_t)BROWS * HDIM];
__device__ __nv_bfloat16 g_Phi[(size_t)HDIM * HDIM];
__device__ __nv_bfloat16 g_Plo[(size_t)HDIM * HDIM];

// ---------------- helpers ---------------------------------------------------
__device__ __forceinline__ uint32_t smem_u32(const void* p) {
    uint32_t a;
    asm("{ .reg .u64 t; cvta.to.shared.u64 t, %1; cvt.u32.u64 %0, t; }" : "=r"(a) : "l"(p));
    return a;
}
__device__ __forceinline__ void cp16(uint32_t s, const void* g) {
    asm volatile("cp.async.cg.shared.global [%0], [%1], 16;" :: "r"(s), "l"(g));
}
#define CP_COMMIT() asm volatile("cp.async.commit_group;" ::: "memory")
#define CP_WAIT0()  asm volatile("cp.async.wait_group 0;" ::: "memory")

__device__ __forceinline__ void ldsm4(uint32_t* r, uint32_t addr) {
    asm volatile("ldmatrix.sync.aligned.m8n8.x4.shared.b16 {%0,%1,%2,%3}, [%4];"
                 : "=r"(r[0]), "=r"(r[1]), "=r"(r[2]), "=r"(r[3]) : "r"(addr));
}
__device__ __forceinline__ void mma16816(float* d, const uint32_t* a, uint32_t b0, uint32_t b1) {
    asm volatile(
        "mma.sync.aligned.m16n8k16.row.col.f32.bf16.bf16.f32 "
        "{%0,%1,%2,%3}, {%4,%5,%6,%7}, {%8,%9}, {%0,%1,%2,%3};"
        : "+f"(d[0]), "+f"(d[1]), "+f"(d[2]), "+f"(d[3])
        : "r"(a[0]), "r"(a[1]), "r"(a[2]), "r"(a[3]), "r"(b0), "r"(b1));
}
__device__ __forceinline__ float sigmoidf_(float x) { return 1.0f / (1.0f + expf(-x)); }

// smem tile: 128 rows x 32 bf16 (64B/row), 16B-chunk swizzle: c ^= (row>>1)&3
__device__ __forceinline__ uint32_t swadr(uint32_t base, int row, int chunk) {
    return base + row * 64 + ((chunk ^ ((row >> 1) & 3)) << 4);
}

// ---------------------------------------------------------------------------
// cp.async one 128x32 bf16 tile (gmem row-major, ld = K halves) into smem
// ---------------------------------------------------------------------------
__device__ __forceinline__ void load_tile(uint32_t sbase, const __nv_bfloat16* __restrict__ g,
                                          int row0, int koff, int K, int tid)
{
#pragma unroll
    for (int it = 0; it < 2; it++) {
        int l = tid + it * 256;          // 0..511
        int r = l >> 2;                  // 0..127
        int c = l & 3;                   // 16B chunk
        cp16(swadr(sbase, r, c), g + (size_t)(row0 + r) * K + koff + c * 8);
    }
}

// ---------------------------------------------------------------------------
// Split-bf16 GEMM via mma.sync: C[128,128] tile = A[M,K] @ B[N,K]^T
// D += Ahi*Bhi + Alo*Bhi + Ahi*Blo  (fp32 accum)
// 256 threads = 8 warps (2x4), warp tile 64x32, K-chunk 32, double buffer.
// MODE 0: +bias, per-gate activation -> g_act.  MODE 1: plain -> Cout.
// ---------------------------------------------------------------------------
#define T_AHI 0
#define T_ALO 8192
#define T_BHI 16384
#define T_BLO 24576
#define STAGE 32768
#define SMEM_DYN (2 * STAGE)

template <int MODE>
__global__ __launch_bounds__(256)
void gemm_mma(const __nv_bfloat16* __restrict__ Ahi, const __nv_bfloat16* __restrict__ Alo,
              const __nv_bfloat16* __restrict__ Bhi, const __nv_bfloat16* __restrict__ Blo,
              const float* __restrict__ bias, float* __restrict__ Cout, int K)
{
    extern __shared__ char smem[];
    const uint32_t sb = smem_u32(smem);
    const int tid  = threadIdx.x;
    const int wid  = tid >> 5;
    const int lane = tid & 31;
    const int bm = blockIdx.y * 128;
    const int bn = blockIdx.x * 128;
    const int wm = (wid >> 2) * 64;      // warp M offset (0 or 64)
    const int wn = (wid & 3) * 32;       // warp N offset
    const int nch = K / 32;

    const int lg = lane >> 3;            // ldmatrix lane group 0..3
    const int lr = lane & 7;

    float acc[4][4][4];
#pragma unroll
    for (int i = 0; i < 4; i++)
#pragma unroll
        for (int j = 0; j < 4; j++)
#pragma unroll
            for (int e = 0; e < 4; e++) acc[i][j][e] = 0.0f;

    // prologue
    load_tile(sb + T_AHI, Ahi, bm, 0, K, tid);
    load_tile(sb + T_ALO, Alo, bm, 0, K, tid);
    load_tile(sb + T_BHI, Bhi, bn, 0, K, tid);
    load_tile(sb + T_BLO, Blo, bn, 0, K, tid);
    CP_COMMIT();

    for (int c = 0; c < nch; c++) {
        const uint32_t cur = sb + (c & 1) * STAGE;
        const uint32_t nxt = sb + ((c + 1) & 1) * STAGE;
        CP_WAIT0();
        __syncthreads();
        if (c + 1 < nch) {
            int ko = (c + 1) * 32;
            load_tile(nxt + T_AHI, Ahi, bm, ko, K, tid);
            load_tile(nxt + T_ALO, Alo, bm, ko, K, tid);
            load_tile(nxt + T_BHI, Bhi, bn, ko, K, tid);
            load_tile(nxt + T_BLO, Blo, bn, ko, K, tid);
            CP_COMMIT();
        }

#pragma unroll
        for (int ka = 0; ka < 2; ka++) {
            const int kc = ka * 2;       // 16B-chunk index of this k-atom

            // A-fragment addresses: tiles (m0,k0)(m8,k0)(m0,k8)(m8,k8)
            // lane group g: row = mo + lr + (g&1)*8 ; chunk = kc + (g>>1)
            const int arow_off = lr + (lg & 1) * 8;
            const int achk     = kc + (lg >> 1);
            // B-fragment: tiles (n0,k0)(n0,k8)(n8,k0)(n8,k8)
            const int brow_off = lr + (lg >> 1) * 8;
            const int bchk     = kc + (lg & 1);

            uint32_t ah[4][4];
#pragma unroll
            for (int i = 0; i < 4; i++)
                ldsm4(ah[i], swadr(cur + T_AHI, wm + i * 16 + arow_off, achk));
            uint32_t bh[2][4];
#pragma unroll
            for (int j = 0; j < 2; j++)
                ldsm4(bh[j], swadr(cur + T_BHI, wn + j * 16 + brow_off, bchk));

            // hi * hi
#pragma unroll
            for (int i = 0; i < 4; i++)
#pragma unroll
                for (int j = 0; j < 2; j++) {
                    mma16816(acc[i][2 * j + 0], ah[i], bh[j][0], bh[j][1]);
                    mma16816(acc[i][2 * j + 1], ah[i], bh[j][2], bh[j][3]);
                }

            // lo * hi
            uint32_t al[4][4];
#pragma unroll
            for (int i = 0; i < 4; i++)
                ldsm4(al[i], swadr(cur + T_ALO, wm + i * 16 + arow_off, achk));
#pragma unroll
            for (int i = 0; i < 4; i++)
#pragma unroll
                for (int j = 0; j < 2; j++) {
                    mma16816(acc[i][2 * j + 0], al[i], bh[j][0], bh[j][1]);
                    mma16816(acc[i][2 * j + 1], al[i], bh[j][2], bh[j][3]);
                }

            // hi * lo
            uint32_t bl[2][4];
#pragma unroll
            for (int j = 0; j < 2; j++)
                ldsm4(bl[j], swadr(cur + T_BLO, wn + j * 16 + brow_off, bchk));
#pragma unroll
            for (int i = 0; i < 4; i++)
#pragma unroll
                for (int j = 0; j < 2; j++) {
                    mma16816(acc[i][2 * j + 0], ah[i], bl[j][0], bl[j][1]);
                    mma16816(acc[i][2 * j + 1], ah[i], bl[j][2], bl[j][3]);
                }
        }
    }

    // ---------------- epilogue: registers -> gmem ---------------------------
    const int er = lane >> 2;            // 0..7
    const int ec = (lane & 3) * 2;
#pragma unroll
    for (int i = 0; i < 4; i++) {
#pragma unroll
        for (int j = 0; j < 4; j++) {
#pragma unroll
            for (int half = 0; half < 2; half++) {
                int grow = bm + wm + i * 16 + er + half * 8;
                int gcol = bn + wn + j * 8 + ec;
                float v0 = acc[i][j][half * 2 + 0];
                float v1 = acc[i][j][half * 2 + 1];
                if (MODE == 0) {
                    v0 += bias[gcol];
                    v1 += bias[gcol + 1];
                    int gate = gcol >> 9;            // 0:i 1:f 2:g 3:o
                    v0 = (gate == 2) ? tanhf(v0) : sigmoidf_(v0);
                    v1 = (gate == 2) ? tanhf(v1) : sigmoidf_(v1);
                    *reinterpret_cast<float2*>(&g_act[(size_t)grow * NDIM1 + gcol]) =
                        make_float2(v0, v1);
                } else {
                    *reinterpret_cast<float2*>(&Cout[(size_t)grow * HDIM + gcol]) =
                        make_float2(v0, v1);
                }
            }
        }
    }
}

// ---------------------------------------------------------------------------
// fp32 -> bf16 hi/lo split conversions
// ---------------------------------------------------------------------------
__device__ __forceinline__ void split1(float v, __nv_bfloat16* hi, __nv_bfloat16* lo) {
    __nv_bfloat16 h = __float2bfloat16(v);
    *hi = h;
    *lo = __float2bfloat16(v - __bfloat162float(h));
}

__global__ __launch_bounds__(256)
void conv_A(const float* __restrict__ x, const float* __restrict__ h)
{
    size_t i = ((size_t)blockIdx.x * blockDim.x + threadIdx.x) * 4;   // 16384*1024 total
    int row = (int)(i >> 10), col = (int)(i & 1023);
    const float* src = (col < 512) ? (x + (size_t)row * 512 + col)
                                   : (h + (size_t)row * 512 + (col - 512));
    float4 v = *reinterpret_cast<const float4*>(src);
    split1(v.x, &g_Ahi[i + 0], &g_Alo[i + 0]);
    split1(v.y, &g_Ahi[i + 1], &g_Alo[i + 1]);
    split1(v.z, &g_Ahi[i + 2], &g_Alo[i + 2]);
    split1(v.w, &g_Ahi[i + 3], &g_Alo[i + 3]);
}

__global__ __launch_bounds__(256)
void conv_W(const float* __restrict__ src, __nv_bfloat16* __restrict__ hi,
            __nv_bfloat16* __restrict__ lo, int n4)
{
    int i = blockIdx.x * blockDim.x + threadIdx.x;
    if (i >= n4) return;
    float4 v = reinterpret_cast<const float4*>(src)[i];
    size_t b = (size_t)i * 4;
    split1(v.x, &hi[b + 0], &lo[b + 0]);
    split1(v.y, &hi[b + 1], &lo[b + 1]);
    split1(v.z, &hi[b + 2], &lo[b + 2]);
    split1(v.w, &hi[b + 3], &lo[b + 3]);
}

// ---------------------------------------------------------------------------
// LayerNorm + cell + s = o*tanh(cell)  (writes cell fp32, s as bf16 hi/lo)
// ---------------------------------------------------------------------------
__global__ __launch_bounds__(512)
void ln_kernel(const float* __restrict__ c_prev,
               const float* __restrict__ gamma,
               const float* __restrict__ beta,
               float* __restrict__ out_cell)
{
    const int b = blockIdx.x;
    const int h = threadIdx.x;
    const float* row = g_act + (size_t)b * NDIM1;

    float ig = row[h];
    float fg = row[HDIM + h];
    float gg = row[2 * HDIM + h];
    float og = row[3 * HDIM + h];

    float c = fg * c_prev[(size_t)b * HDIM + h] + ig * gg;

    __shared__ float s_sum[512];
    __shared__ float s_sq[512];
    s_sum[h] = c;
    s_sq[h]  = c * c;
    __syncthreads();
#pragma unroll
    for (int ofs = 256; ofs > 0; ofs >>= 1) {
        if (h < ofs) {
            s_sum[h] += s_sum[h + ofs];
            s_sq[h]  += s_sq[h + ofs];
        }
        __syncthreads();
    }
    float mu  = s_sum[0] * (1.0f / HDIM);
    float var = s_sq[0] * (1.0f / HDIM) - mu * mu;
    float inv = rsqrtf(var + LN_EPS);

    float cn = (c - mu) * inv * gamma[h] + beta[h];
    out_cell[(size_t)b * HDIM + h] = cn;
    float s = og * tanhf(cn);
    split1(s, &g_Shi[(size_t)b * HDIM + h], &g_Slo[(size_t)b * HDIM + h]);
}

// ---------------------------------------------------------------------------
extern "C" void kernel_launch(void* const* d_in, const int* in_sizes, int n_in,
                              void* d_out, int out_size)
{
    const float* x      = (const float*)d_in[0];
    const float* h_prev = (const float*)d_in[1];
    const float* c_prev = (const float*)d_in[2];
    const float* W      = (const float*)d_in[3];
    const float* b      = (const float*)d_in[4];
    const float* gamma  = (const float*)d_in[5];
    const float* beta   = (const float*)d_in[6];
    const float* Wp     = (const float*)d_in[7];
    float* out = (float*)d_out;                       // [out | cell]
    float* out_cell = out + (size_t)BROWS * HDIM;

    cudaFuncSetAttribute(gemm_mma<0>, cudaFuncAttributeMaxDynamicSharedMemorySize, SMEM_DYN);
    cudaFuncSetAttribute(gemm_mma<1>, cudaFuncAttributeMaxDynamicSharedMemorySize, SMEM_DYN);

    __nv_bfloat16 *pAhi, *pAlo, *pWhi, *pWlo, *pShi, *pSlo, *pPhi, *pPlo;
    cudaGetSymbolAddress((void**)&pAhi, g_Ahi);
    cudaGetSymbolAddress((void**)&pAlo, g_Alo);
    cudaGetSymbolAddress((void**)&pWhi, g_Whi);
    cudaGetSymbolAddress((void**)&pWlo, g_Wlo);
    cudaGetSymbolAddress((void**)&pShi, g_Shi);
    cudaGetSymbolAddress((void**)&pSlo, g_Slo);
    cudaGetSymbolAddress((void**)&pPhi, g_Phi);
    cudaGetSymbolAddress((void**)&pPlo, g_Plo);

    // fp32 -> bf16 splits
    conv_A<<<(BROWS * KDIM1 / 4) / 256, 256>>>(x, h_prev);
    conv_W<<<(NDIM1 * KDIM1 / 4 + 255) / 256, 256>>>(W, pWhi, pWlo, NDIM1 * KDIM1 / 4);
    conv_W<<<(HDIM * HDIM / 4 + 255) / 256, 256>>>(Wp, pPhi, pPlo, HDIM * HDIM / 4);

    // GEMM1: gates (+bias, +activation) -> g_act
    gemm_mma<0><<<dim3(NDIM1 / 128, BROWS / 128), 256, SMEM_DYN>>>(
        pAhi, pAlo, pWhi, pWlo, b, nullptr, KDIM1);

    // LayerNorm + cell + s (bf16 split)
    ln_kernel<<<BROWS, 512>>>(c_prev, gamma, beta, out_cell);

    // GEMM2: out = s @ Wp^T
    gemm_mma<1><<<dim3(HDIM / 128, BROWS / 128), 256, SMEM_DYN>>>(
        pShi, pSlo, pPhi, pPlo, nullptr, out, HDIM);
}

// round 8
// speedup vs baseline: 2.7926x; 1.1612x over previous
#include <cuda_runtime.h>
#include <cuda_bf16.h>
#include <math.h>
#include <stdint.h>

#define BROWS 16384
#define HDIM  512
#define KDIM1 1024   // I + H
#define NDIM1 2048   // 4*H
#define LN_EPS 1e-5f

// ---------------- scratch (device globals; allocation-free rule) -----------
// g_cell = pre-LN cell state, g_og = sigmoid(o)   (each 32MB fp32)
__device__ float g_cell[(size_t)BROWS * HDIM];
__device__ float g_og  [(size_t)BROWS * HDIM];
__device__ __nv_bfloat16 g_Ahi[(size_t)BROWS * KDIM1];
__device__ __nv_bfloat16 g_Alo[(size_t)BROWS * KDIM1];
__device__ __nv_bfloat16 g_Whi[(size_t)NDIM1 * KDIM1];   // gate-interleaved rows: 4h+gate
__device__ __nv_bfloat16 g_Wlo[(size_t)NDIM1 * KDIM1];
__device__ __nv_bfloat16 g_Shi[(size_t)BROWS * HDIM];
__device__ __nv_bfloat16 g_Slo[(size_t)BROWS * HDIM];
__device__ __nv_bfloat16 g_Phi[(size_t)HDIM * HDIM];
__device__ __nv_bfloat16 g_Plo[(size_t)HDIM * HDIM];

// ---------------- helpers ---------------------------------------------------
__device__ __forceinline__ uint32_t smem_u32(const void* p) {
    uint32_t a;
    asm("{ .reg .u64 t; cvta.to.shared.u64 t, %1; cvt.u32.u64 %0, t; }" : "=r"(a) : "l"(p));
    return a;
}
__device__ __forceinline__ void cp16(uint32_t s, const void* g) {
    asm volatile("cp.async.cg.shared.global [%0], [%1], 16;" :: "r"(s), "l"(g));
}
#define CP_COMMIT() asm volatile("cp.async.commit_group;" ::: "memory")
#define CP_WAIT0()  asm volatile("cp.async.wait_group 0;" ::: "memory")

__device__ __forceinline__ void ldsm4(uint32_t* r, uint32_t addr) {
    asm volatile("ldmatrix.sync.aligned.m8n8.x4.shared.b16 {%0,%1,%2,%3}, [%4];"
                 : "=r"(r[0]), "=r"(r[1]), "=r"(r[2]), "=r"(r[3]) : "r"(addr));
}
__device__ __forceinline__ void mma16816(float* d, const uint32_t* a, uint32_t b0, uint32_t b1) {
    asm volatile(
        "mma.sync.aligned.m16n8k16.row.col.f32.bf16.bf16.f32 "
        "{%0,%1,%2,%3}, {%4,%5,%6,%7}, {%8,%9}, {%0,%1,%2,%3};"
        : "+f"(d[0]), "+f"(d[1]), "+f"(d[2]), "+f"(d[3])
        : "r"(a[0]), "r"(a[1]), "r"(a[2]), "r"(a[3]), "r"(b0), "r"(b1));
}
__device__ __forceinline__ float sigmoidf_(float x) { return 1.0f / (1.0f + expf(-x)); }

// smem tile: 128 rows x 32 bf16 (64B/row), 16B-chunk swizzle: c ^= (row>>1)&3
__device__ __forceinline__ uint32_t swadr(uint32_t base, int row, int chunk) {
    return base + row * 64 + ((chunk ^ ((row >> 1) & 3)) << 4);
}

__device__ __forceinline__ void load_tile(uint32_t sbase, const __nv_bfloat16* __restrict__ g,
                                          int row0, int koff, int K, int tid)
{
#pragma unroll
    for (int it = 0; it < 2; it++) {
        int l = tid + it * 256;          // 0..511
        int r = l >> 2;                  // 0..127
        int c = l & 3;                   // 16B chunk
        cp16(swadr(sbase, r, c), g + (size_t)(row0 + r) * K + koff + c * 8);
    }
}

// ---------------------------------------------------------------------------
// Split-bf16 GEMM via mma.sync: C[128,128] tile = A[M,K] @ B[N,K]^T
// D += Ahi*Bhi + Alo*Bhi + Ahi*Blo  (fp32 accum)
// 256 threads = 8 warps (2x4), warp tile 64x32, K-chunk 32, double buffer.
// MODE 0: W gate-interleaved; epilogue computes cell + sigmoid(o) directly.
// MODE 1: plain -> Cout (float2 stores).
// ---------------------------------------------------------------------------
#define T_AHI 0
#define T_ALO 8192
#define T_BHI 16384
#define T_BLO 24576
#define STAGE 32768
#define SMEM_DYN (2 * STAGE)

template <int MODE>
__global__ __launch_bounds__(256, 2)
void gemm_mma(const __nv_bfloat16* __restrict__ Ahi, const __nv_bfloat16* __restrict__ Alo,
              const __nv_bfloat16* __restrict__ Bhi, const __nv_bfloat16* __restrict__ Blo,
              const float* __restrict__ bias, const float* __restrict__ c_prev,
              float* __restrict__ Cout, int K)
{
    extern __shared__ char smem[];
    const uint32_t sb = smem_u32(smem);
    const int tid  = threadIdx.x;
    const int wid  = tid >> 5;
    const int lane = tid & 31;
    const int bm = blockIdx.y * 128;
    const int bn = blockIdx.x * 128;
    const int wm = (wid >> 2) * 64;      // warp M offset (0 or 64)
    const int wn = (wid & 3) * 32;       // warp N offset
    const int nch = K / 32;

    const int lg = lane >> 3;            // ldmatrix lane group 0..3
    const int lr = lane & 7;

    float acc[4][4][4];
#pragma unroll
    for (int i = 0; i < 4; i++)
#pragma unroll
        for (int j = 0; j < 4; j++)
#pragma unroll
            for (int e = 0; e < 4; e++) acc[i][j][e] = 0.0f;

    // prologue
    load_tile(sb + T_AHI, Ahi, bm, 0, K, tid);
    load_tile(sb + T_ALO, Alo, bm, 0, K, tid);
    load_tile(sb + T_BHI, Bhi, bn, 0, K, tid);
    load_tile(sb + T_BLO, Blo, bn, 0, K, tid);
    CP_COMMIT();

    for (int c = 0; c < nch; c++) {
        const uint32_t cur = sb + (c & 1) * STAGE;
        const uint32_t nxt = sb + ((c + 1) & 1) * STAGE;
        CP_WAIT0();
        __syncthreads();
        if (c + 1 < nch) {
            int ko = (c + 1) * 32;
            load_tile(nxt + T_AHI, Ahi, bm, ko, K, tid);
            load_tile(nxt + T_ALO, Alo, bm, ko, K, tid);
            load_tile(nxt + T_BHI, Bhi, bn, ko, K, tid);
            load_tile(nxt + T_BLO, Blo, bn, ko, K, tid);
            CP_COMMIT();
        }

#pragma unroll
        for (int ka = 0; ka < 2; ka++) {
            const int kc = ka * 2;       // 16B-chunk index of this k-atom
            const int arow_off = lr + (lg & 1) * 8;
            const int achk     = kc + (lg >> 1);
            const int brow_off = lr + (lg >> 1) * 8;
            const int bchk     = kc + (lg & 1);

            uint32_t ah[4][4];
#pragma unroll
            for (int i = 0; i < 4; i++)
                ldsm4(ah[i], swadr(cur + T_AHI, wm + i * 16 + arow_off, achk));
            uint32_t bh[2][4];
#pragma unroll
            for (int j = 0; j < 2; j++)
                ldsm4(bh[j], swadr(cur + T_BHI, wn + j * 16 + brow_off, bchk));

            // hi * hi
#pragma unroll
            for (int i = 0; i < 4; i++)
#pragma unroll
                for (int j = 0; j < 2; j++) {
                    mma16816(acc[i][2 * j + 0], ah[i], bh[j][0], bh[j][1]);
                    mma16816(acc[i][2 * j + 1], ah[i], bh[j][2], bh[j][3]);
                }

            // hi * lo  (keeps ah live, frees it before al arrives)
            uint32_t bl[2][4];
#pragma unroll
            for (int j = 0; j < 2; j++)
                ldsm4(bl[j], swadr(cur + T_BLO, wn + j * 16 + brow_off, bchk));
#pragma unroll
            for (int i = 0; i < 4; i++)
#pragma unroll
                for (int j = 0; j < 2; j++) {
                    mma16816(acc[i][2 * j + 0], ah[i], bl[j][0], bl[j][1]);
                    mma16816(acc[i][2 * j + 1], ah[i], bl[j][2], bl[j][3]);
                }

            // lo * hi
            uint32_t al[4][4];
#pragma unroll
            for (int i = 0; i < 4; i++)
                ldsm4(al[i], swadr(cur + T_ALO, wm + i * 16 + arow_off, achk));
#pragma unroll
            for (int i = 0; i < 4; i++)
#pragma unroll
                for (int j = 0; j < 2; j++) {
                    mma16816(acc[i][2 * j + 0], al[i], bh[j][0], bh[j][1]);
                    mma16816(acc[i][2 * j + 1], al[i], bh[j][2], bh[j][3]);
                }
        }
    }

    // ---------------- epilogue ---------------------------------------------
    const int er = lane >> 2;            // 0..7
    const int ec = (lane & 3) * 2;       // 0,2,4,6
    const bool isIF = ((lane & 1) == 0); // even lane pairs hold (i,f), odd (g,o)
#pragma unroll
    for (int i = 0; i < 4; i++) {
#pragma unroll
        for (int j = 0; j < 4; j++) {
#pragma unroll
            for (int half = 0; half < 2; half++) {
                int grow = bm + wm + i * 16 + er + half * 8;
                int gcol = bn + wn + j * 8 + ec;
                float v0 = acc[i][j][half * 2 + 0];
                float v1 = acc[i][j][half * 2 + 1];
                if (MODE == 0) {
                    // gate-interleaved cols: gcol = 4h + gate
                    int h     = gcol >> 2;
                    int gate0 = gcol & 3;                 // 0 (i) or 2 (g)
                    v0 += bias[gate0 * HDIM + h];
                    v1 += bias[(gate0 + 1) * HDIM + h];
                    float a0 = (gate0 == 2) ? tanhf(v0) : sigmoidf_(v0);  // i or g
                    float a1 = sigmoidf_(v1);                             // f or o
                    float p0 = __shfl_xor_sync(0xffffffffu, a0, 1);
                    __shfl_xor_sync(0xffffffffu, a1, 1);   // keep lockstep (p1 unused)
                    size_t idx = (size_t)grow * HDIM + h;
                    if (isIF) {
                        // a0=sig(i), a1=sig(f), p0=tanh(g)
                        g_cell[idx] = a1 * c_prev[idx] + a0 * p0;
                    } else {
                        // a1 = sig(o)
                        g_og[idx] = a1;
                    }
                } else {
                    *reinterpret_cast<float2*>(&Cout[(size_t)grow * HDIM + gcol]) =
                        make_float2(v0, v1);
                }
            }
        }
    }
}

// ---------------------------------------------------------------------------
// fp32 -> bf16 hi/lo split conversions
// ---------------------------------------------------------------------------
__device__ __forceinline__ void split1(float v, __nv_bfloat16* hi, __nv_bfloat16* lo) {
    __nv_bfloat16 h = __float2bfloat16(v);
    *hi = h;
    *lo = __float2bfloat16(v - __bfloat162float(h));
}

__global__ __launch_bounds__(256)
void conv_A(const float* __restrict__ x, const float* __restrict__ h)
{
    size_t i = ((size_t)blockIdx.x * blockDim.x + threadIdx.x) * 4;   // 16384*1024 total
    int row = (int)(i >> 10), col = (int)(i & 1023);
    const float* src = (col < 512) ? (x + (size_t)row * 512 + col)
                                   : (h + (size_t)row * 512 + (col - 512));
    float4 v = *reinterpret_cast<const float4*>(src);
    split1(v.x, &g_Ahi[i + 0], &g_Alo[i + 0]);
    split1(v.y, &g_Ahi[i + 1], &g_Alo[i + 1]);
    split1(v.z, &g_Ahi[i + 2], &g_Alo[i + 2]);
    split1(v.w, &g_Ahi[i + 3], &g_Alo[i + 3]);
}

// PERM: scatter old row r -> new row 4*(r%512) + (r/512)  (gate interleave)
template <bool PERM>
__global__ __launch_bounds__(256)
void conv_W(const float* __restrict__ src, __nv_bfloat16* __restrict__ hi,
            __nv_bfloat16* __restrict__ lo, int K, int n4)
{
    int i = blockIdx.x * blockDim.x + threadIdx.x;
    if (i >= n4) return;
    float4 v = reinterpret_cast<const float4*>(src)[i];
    size_t e = (size_t)i * 4;
    int r = (int)(e / K), col = (int)(e % K);
    int nr = PERM ? ((r & 511) * 4 + (r >> 9)) : r;
    size_t b = (size_t)nr * K + col;
    split1(v.x, &hi[b + 0], &lo[b + 0]);
    split1(v.y, &hi[b + 1], &lo[b + 1]);
    split1(v.z, &hi[b + 2], &lo[b + 2]);
    split1(v.w, &hi[b + 3], &lo[b + 3]);
}

// ---------------------------------------------------------------------------
// LayerNorm over pre-LN cell + s = sigmoid(o)*tanh(cell_ln)
// ---------------------------------------------------------------------------
__global__ __launch_bounds__(512)
void ln_kernel(const float* __restrict__ gamma,
               const float* __restrict__ beta,
               float* __restrict__ out_cell)
{
    const int b = blockIdx.x;
    const int h = threadIdx.x;
    const size_t idx = (size_t)b * HDIM + h;

    float c = g_cell[idx];

    __shared__ float s_sum[512];
    __shared__ float s_sq[512];
    s_sum[h] = c;
    s_sq[h]  = c * c;
    __syncthreads();
#pragma unroll
    for (int ofs = 256; ofs > 0; ofs >>= 1) {
        if (h < ofs) {
            s_sum[h] += s_sum[h + ofs];
            s_sq[h]  += s_sq[h + ofs];
        }
        __syncthreads();
    }
    float mu  = s_sum[0] * (1.0f / HDIM);
    float var = s_sq[0] * (1.0f / HDIM) - mu * mu;
    float inv = rsqrtf(var + LN_EPS);

    float cn = (c - mu) * inv * gamma[h] + beta[h];
    out_cell[idx] = cn;
    float s = g_og[idx] * tanhf(cn);
    split1(s, &g_Shi[idx], &g_Slo[idx]);
}

// ---------------------------------------------------------------------------
extern "C" void kernel_launch(void* const* d_in, const int* in_sizes, int n_in,
                              void* d_out, int out_size)
{
    const float* x      = (const float*)d_in[0];
    const float* h_prev = (const float*)d_in[1];
    const float* c_prev = (const float*)d_in[2];
    const float* W      = (const float*)d_in[3];
    const float* b      = (const float*)d_in[4];
    const float* gamma  = (const float*)d_in[5];
    const float* beta   = (const float*)d_in[6];
    const float* Wp     = (const float*)d_in[7];
    float* out = (float*)d_out;                       // [out | cell]
    float* out_cell = out + (size_t)BROWS * HDIM;

    cudaFuncSetAttribute(gemm_mma<0>, cudaFuncAttributeMaxDynamicSharedMemorySize, SMEM_DYN);
    cudaFuncSetAttribute(gemm_mma<1>, cudaFuncAttributeMaxDynamicSharedMemorySize, SMEM_DYN);

    __nv_bfloat16 *pAhi, *pAlo, *pWhi, *pWlo, *pShi, *pSlo, *pPhi, *pPlo;
    cudaGetSymbolAddress((void**)&pAhi, g_Ahi);
    cudaGetSymbolAddress((void**)&pAlo, g_Alo);
    cudaGetSymbolAddress((void**)&pWhi, g_Whi);
    cudaGetSymbolAddress((void**)&pWlo, g_Wlo);
    cudaGetSymbolAddress((void**)&pShi, g_Shi);
    cudaGetSymbolAddress((void**)&pSlo, g_Slo);
    cudaGetSymbolAddress((void**)&pPhi, g_Phi);
    cudaGetSymbolAddress((void**)&pPlo, g_Plo);

    // fp32 -> bf16 splits (W gate-interleaved)
    conv_A<<<(BROWS * KDIM1 / 4) / 256, 256>>>(x, h_prev);
    conv_W<true ><<<(NDIM1 * KDIM1 / 4 + 255) / 256, 256>>>(W,  pWhi, pWlo, KDIM1, NDIM1 * KDIM1 / 4);
    conv_W<false><<<(HDIM * HDIM / 4 + 255) / 256, 256>>>(Wp, pPhi, pPlo, HDIM,  HDIM * HDIM / 4);

    // GEMM1: gates + fused bias/activation/cell -> g_cell, g_og
    gemm_mma<0><<<dim3(NDIM1 / 128, BROWS / 128), 256, SMEM_DYN>>>(
        pAhi, pAlo, pWhi, pWlo, b, c_prev, nullptr, KDIM1);

    // LayerNorm + s (bf16 split)
    ln_kernel<<<BROWS, 512>>>(gamma, beta, out_cell);

    // GEMM2: out = s @ Wp^T
    gemm_mma<1><<<dim3(HDIM / 128, BROWS / 128), 256, SMEM_DYN>>>(
        pShi, pSlo, pPhi, pPlo, nullptr, nullptr, out, HDIM);
}

// round 9
// speedup vs baseline: 2.9700x; 1.0635x over previous
#include <cuda_runtime.h>
#include <cuda_bf16.h>
#include <math.h>
#include <stdint.h>

#define BROWS 16384
#define HDIM  512
#define KDIM1 1024   // I + H
#define NDIM1 2048   // 4*H
#define LN_EPS 1e-5f

// ---------------- scratch (device globals; allocation-free rule) -----------
__device__ float g_cell[(size_t)BROWS * HDIM];
__device__ float g_og  [(size_t)BROWS * HDIM];
__device__ __nv_bfloat16 g_Ahi[(size_t)BROWS * KDIM1];
__device__ __nv_bfloat16 g_Alo[(size_t)BROWS * KDIM1];
__device__ __nv_bfloat16 g_Whi[(size_t)NDIM1 * KDIM1];   // gate-interleaved rows: 4h+gate
__device__ __nv_bfloat16 g_Wlo[(size_t)NDIM1 * KDIM1];
__device__ __nv_bfloat16 g_Shi[(size_t)BROWS * HDIM];
__device__ __nv_bfloat16 g_Slo[(size_t)BROWS * HDIM];
__device__ __nv_bfloat16 g_Phi[(size_t)HDIM * HDIM];
__device__ __nv_bfloat16 g_Plo[(size_t)HDIM * HDIM];

// ---------------- helpers ---------------------------------------------------
__device__ __forceinline__ uint32_t smem_u32(const void* p) {
    uint32_t a;
    asm("{ .reg .u64 t; cvta.to.shared.u64 t, %1; cvt.u32.u64 %0, t; }" : "=r"(a) : "l"(p));
    return a;
}
__device__ __forceinline__ void cp16(uint32_t s, const void* g) {
    asm volatile("cp.async.cg.shared.global [%0], [%1], 16;" :: "r"(s), "l"(g));
}
#define CP_COMMIT() asm volatile("cp.async.commit_group;" ::: "memory")
#define CP_WAIT(n)  asm volatile("cp.async.wait_group %0;" :: "n"(n) : "memory")

__device__ __forceinline__ void ldsm4(uint32_t* r, uint32_t addr) {
    asm volatile("ldmatrix.sync.aligned.m8n8.x4.shared.b16 {%0,%1,%2,%3}, [%4];"
                 : "=r"(r[0]), "=r"(r[1]), "=r"(r[2]), "=r"(r[3]) : "r"(addr));
}
__device__ __forceinline__ void mma16816(float* d, const uint32_t* a, uint32_t b0, uint32_t b1) {
    asm volatile(
        "mma.sync.aligned.m16n8k16.row.col.f32.bf16.bf16.f32 "
        "{%0,%1,%2,%3}, {%4,%5,%6,%7}, {%8,%9}, {%0,%1,%2,%3};"
        : "+f"(d[0]), "+f"(d[1]), "+f"(d[2]), "+f"(d[3])
        : "r"(a[0]), "r"(a[1]), "r"(a[2]), "r"(a[3]), "r"(b0), "r"(b1));
}
__device__ __forceinline__ float sigmoidf_(float x) { return 1.0f / (1.0f + expf(-x)); }

// smem tile: 128 rows x 32 bf16 (64B/row), 16B-chunk swizzle: c ^= (row>>1)&3
__device__ __forceinline__ uint32_t swadr(uint32_t base, int row, int chunk) {
    return base + row * 64 + ((chunk ^ ((row >> 1) & 3)) << 4);
}

__device__ __forceinline__ void load_tile(uint32_t sbase, const __nv_bfloat16* __restrict__ g,
                                          int row0, int koff, int K, int tid)
{
#pragma unroll
    for (int it = 0; it < 2; it++) {
        int l = tid + it * 256;          // 0..511
        int r = l >> 2;                  // 0..127
        int c = l & 3;                   // 16B chunk
        cp16(swadr(sbase, r, c), g + (size_t)(row0 + r) * K + koff + c * 8);
    }
}

// ---------------------------------------------------------------------------
// Split-bf16 GEMM via mma.sync, 3-stage cp.async pipeline (wait_group 1).
// C[128,128] tile = A[M,K] @ B[N,K]^T ;  D += Ahi*Bhi + Ahi*Blo + Alo*Bhi
// 256 threads = 8 warps (2x4), warp tile 64x32, K-chunk 32.
// MODE 0: W gate-interleaved; epilogue computes cell + sigmoid(o) directly.
// MODE 1: plain -> Cout (float2 stores).
// ---------------------------------------------------------------------------
#define T_AHI 0
#define T_ALO 8192
#define T_BHI 16384
#define T_BLO 24576
#define STAGE 32768
#define NSTAGE 3
#define SMEM_DYN (NSTAGE * STAGE)

template <int MODE>
__global__ __launch_bounds__(256, 2)
void gemm_mma(const __nv_bfloat16* __restrict__ Ahi, const __nv_bfloat16* __restrict__ Alo,
              const __nv_bfloat16* __restrict__ Bhi, const __nv_bfloat16* __restrict__ Blo,
              const float* __restrict__ bias, const float* __restrict__ c_prev,
              float* __restrict__ Cout, int K)
{
    extern __shared__ char smem[];
    const uint32_t sb = smem_u32(smem);
    const int tid  = threadIdx.x;
    const int wid  = tid >> 5;
    const int lane = tid & 31;
    const int bm = blockIdx.y * 128;
    const int bn = blockIdx.x * 128;
    const int wm = (wid >> 2) * 64;      // warp M offset (0 or 64)
    const int wn = (wid & 3) * 32;       // warp N offset
    const int nch = K / 32;

    const int lg = lane >> 3;            // ldmatrix lane group 0..3
    const int lr = lane & 7;

    float acc[4][4][4];
#pragma unroll
    for (int i = 0; i < 4; i++)
#pragma unroll
        for (int j = 0; j < 4; j++)
#pragma unroll
            for (int e = 0; e < 4; e++) acc[i][j][e] = 0.0f;

    // prologue: stages 0 and 1
#pragma unroll
    for (int p = 0; p < 2; p++) {
        uint32_t st = sb + p * STAGE;
        int ko = p * 32;
        load_tile(st + T_AHI, Ahi, bm, ko, K, tid);
        load_tile(st + T_ALO, Alo, bm, ko, K, tid);
        load_tile(st + T_BHI, Bhi, bn, ko, K, tid);
        load_tile(st + T_BLO, Blo, bn, ko, K, tid);
        CP_COMMIT();
    }

    int cur_s = 0, nxt_s = 2;
    for (int c = 0; c < nch; c++) {
        const uint32_t cur = sb + cur_s * STAGE;
        CP_WAIT(1);                      // stage c resident (<=1 group pending)
        __syncthreads();                 // all warps done with stage (c-1) => nxt_s reusable
        if (c + 2 < nch) {
            const uint32_t nxt = sb + nxt_s * STAGE;
            int ko = (c + 2) * 32;
            load_tile(nxt + T_AHI, Ahi, bm, ko, K, tid);
            load_tile(nxt + T_ALO, Alo, bm, ko, K, tid);
            load_tile(nxt + T_BHI, Bhi, bn, ko, K, tid);
            load_tile(nxt + T_BLO, Blo, bn, ko, K, tid);
            CP_COMMIT();
        } else {
            CP_COMMIT();                 // keep group count in step for CP_WAIT(1)
        }

#pragma unroll
        for (int ka = 0; ka < 2; ka++) {
            const int kc = ka * 2;       // 16B-chunk index of this k-atom
            const int arow_off = lr + (lg & 1) * 8;
            const int achk     = kc + (lg >> 1);
            const int brow_off = lr + (lg >> 1) * 8;
            const int bchk     = kc + (lg & 1);

            uint32_t ah[4][4];
#pragma unroll
            for (int i = 0; i < 4; i++)
                ldsm4(ah[i], swadr(cur + T_AHI, wm + i * 16 + arow_off, achk));
            uint32_t bh[2][4];
#pragma unroll
            for (int j = 0; j < 2; j++)
                ldsm4(bh[j], swadr(cur + T_BHI, wn + j * 16 + brow_off, bchk));

            // hi * hi
#pragma unroll
            for (int i = 0; i < 4; i++)
#pragma unroll
                for (int j = 0; j < 2; j++) {
                    mma16816(acc[i][2 * j + 0], ah[i], bh[j][0], bh[j][1]);
                    mma16816(acc[i][2 * j + 1], ah[i], bh[j][2], bh[j][3]);
                }

            // hi * lo
            uint32_t bl[2][4];
#pragma unroll
            for (int j = 0; j < 2; j++)
                ldsm4(bl[j], swadr(cur + T_BLO, wn + j * 16 + brow_off, bchk));
#pragma unroll
            for (int i = 0; i < 4; i++)
#pragma unroll
                for (int j = 0; j < 2; j++) {
                    mma16816(acc[i][2 * j + 0], ah[i], bl[j][0], bl[j][1]);
                    mma16816(acc[i][2 * j + 1], ah[i], bl[j][2], bl[j][3]);
                }

            // lo * hi
            uint32_t al[4][4];
#pragma unroll
            for (int i = 0; i < 4; i++)
                ldsm4(al[i], swadr(cur + T_ALO, wm + i * 16 + arow_off, achk));
#pragma unroll
            for (int i = 0; i < 4; i++)
#pragma unroll
                for (int j = 0; j < 2; j++) {
                    mma16816(acc[i][2 * j + 0], al[i], bh[j][0], bh[j][1]);
                    mma16816(acc[i][2 * j + 1], al[i], bh[j][2], bh[j][3]);
                }
        }
        cur_s = (cur_s == 2) ? 0 : cur_s + 1;
        nxt_s = (nxt_s == 2) ? 0 : nxt_s + 1;
    }

    // ---------------- epilogue ---------------------------------------------
    const int er = lane >> 2;            // 0..7
    const int ec = (lane & 3) * 2;       // 0,2,4,6
    const bool isIF = ((lane & 1) == 0); // even lane pairs hold (i,f), odd (g,o)
#pragma unroll
    for (int i = 0; i < 4; i++) {
#pragma unroll
        for (int j = 0; j < 4; j++) {
#pragma unroll
            for (int half = 0; half < 2; half++) {
                int grow = bm + wm + i * 16 + er + half * 8;
                int gcol = bn + wn + j * 8 + ec;
                float v0 = acc[i][j][half * 2 + 0];
                float v1 = acc[i][j][half * 2 + 1];
                if (MODE == 0) {
                    int h     = gcol >> 2;
                    int gate0 = gcol & 3;                 // 0 (i) or 2 (g)
                    v0 += bias[gate0 * HDIM + h];
                    v1 += bias[(gate0 + 1) * HDIM + h];
                    float a0 = (gate0 == 2) ? tanhf(v0) : sigmoidf_(v0);  // i or g
                    float a1 = sigmoidf_(v1);                             // f or o
                    float p0 = __shfl_xor_sync(0xffffffffu, a0, 1);
                    __shfl_xor_sync(0xffffffffu, a1, 1);   // keep lockstep
                    size_t idx = (size_t)grow * HDIM + h;
                    if (isIF) {
                        g_cell[idx] = a1 * c_prev[idx] + a0 * p0;  // f*c_prev + i*tanh(g)
                    } else {
                        g_og[idx] = a1;                            // sigmoid(o)
                    }
                } else {
                    *reinterpret_cast<float2*>(&Cout[(size_t)grow * HDIM + gcol]) =
                        make_float2(v0, v1);
                }
            }
        }
    }
}

// ---------------------------------------------------------------------------
// fp32 -> bf16 hi/lo split conversions
// ---------------------------------------------------------------------------
__device__ __forceinline__ void split1(float v, __nv_bfloat16* hi, __nv_bfloat16* lo) {
    __nv_bfloat16 h = __float2bfloat16(v);
    *hi = h;
    *lo = __float2bfloat16(v - __bfloat162float(h));
}

__global__ __launch_bounds__(256)
void conv_A(const float* __restrict__ x, const float* __restrict__ h)
{
    size_t i = ((size_t)blockIdx.x * blockDim.x + threadIdx.x) * 4;
    int row = (int)(i >> 10), col = (int)(i & 1023);
    const float* src = (col < 512) ? (x + (size_t)row * 512 + col)
                                   : (h + (size_t)row * 512 + (col - 512));
    float4 v = *reinterpret_cast<const float4*>(src);
    split1(v.x, &g_Ahi[i + 0], &g_Alo[i + 0]);
    split1(v.y, &g_Ahi[i + 1], &g_Alo[i + 1]);
    split1(v.z, &g_Ahi[i + 2], &g_Alo[i + 2]);
    split1(v.w, &g_Ahi[i + 3], &g_Alo[i + 3]);
}

// PERM: scatter old row r -> new row 4*(r%512) + (r/512)  (gate interleave)
template <bool PERM>
__global__ __launch_bounds__(256)
void conv_W(const float* __restrict__ src, __nv_bfloat16* __restrict__ hi,
            __nv_bfloat16* __restrict__ lo, int K, int n4)
{
    int i = blockIdx.x * blockDim.x + threadIdx.x;
    if (i >= n4) return;
    float4 v = reinterpret_cast<const float4*>(src)[i];
    size_t e = (size_t)i * 4;
    int r = (int)(e / K), col = (int)(e % K);
    int nr = PERM ? ((r & 511) * 4 + (r >> 9)) : r;
    size_t b = (size_t)nr * K + col;
    split1(v.x, &hi[b + 0], &lo[b + 0]);
    split1(v.y, &hi[b + 1], &lo[b + 1]);
    split1(v.z, &hi[b + 2], &lo[b + 2]);
    split1(v.w, &hi[b + 3], &lo[b + 3]);
}

// ---------------------------------------------------------------------------
// LayerNorm: one warp per row (8 rows/block), shfl-only reduction.
// s = sigmoid(o) * tanh(cell_ln) -> bf16 hi/lo split.
// ---------------------------------------------------------------------------
__global__ __launch_bounds__(256)
void ln_kernel(const float* __restrict__ gamma,
               const float* __restrict__ beta,
               float* __restrict__ out_cell)
{
    const int warp = threadIdx.x >> 5;
    const int lane = threadIdx.x & 31;
    const int b = blockIdx.x * 8 + warp;
    const size_t rowbase = (size_t)b * HDIM;

    // 16 values per lane as 4 float4s
    float4 v[4];
#pragma unroll
    for (int q = 0; q < 4; q++)
        v[q] = *reinterpret_cast<const float4*>(&g_cell[rowbase + (q * 32 + lane) * 4]);

    float sum = 0.f, sq = 0.f;
#pragma unroll
    for (int q = 0; q < 4; q++) {
        sum += v[q].x + v[q].y + v[q].z + v[q].w;
        sq  += v[q].x * v[q].x + v[q].y * v[q].y + v[q].z * v[q].z + v[q].w * v[q].w;
    }
#pragma unroll
    for (int o = 16; o > 0; o >>= 1) {
        sum += __shfl_xor_sync(0xffffffffu, sum, o);
        sq  += __shfl_xor_sync(0xffffffffu, sq, o);
    }
    float mu  = sum * (1.0f / HDIM);
    float var = sq * (1.0f / HDIM) - mu * mu;
    float inv = rsqrtf(var + LN_EPS);

#pragma unroll
    for (int q = 0; q < 4; q++) {
        int h0 = (q * 32 + lane) * 4;
        float4 gm = *reinterpret_cast<const float4*>(&gamma[h0]);
        float4 bt = *reinterpret_cast<const float4*>(&beta[h0]);
        float4 og = *reinterpret_cast<const float4*>(&g_og[rowbase + h0]);
        float4 cn;
        cn.x = (v[q].x - mu) * inv * gm.x + bt.x;
        cn.y = (v[q].y - mu) * inv * gm.y + bt.y;
        cn.z = (v[q].z - mu) * inv * gm.z + bt.z;
        cn.w = (v[q].w - mu) * inv * gm.w + bt.w;
        *reinterpret_cast<float4*>(&out_cell[rowbase + h0]) = cn;
        float s0 = og.x * tanhf(cn.x);
        float s1 = og.y * tanhf(cn.y);
        float s2 = og.z * tanhf(cn.z);
        float s3 = og.w * tanhf(cn.w);
        __nv_bfloat16 hi[4], lo[4];
        split1(s0, &hi[0], &lo[0]);
        split1(s1, &hi[1], &lo[1]);
        split1(s2, &hi[2], &lo[2]);
        split1(s3, &hi[3], &lo[3]);
        *reinterpret_cast<uint64_t*>(&g_Shi[rowbase + h0]) = *reinterpret_cast<uint64_t*>(hi);
        *reinterpret_cast<uint64_t*>(&g_Slo[rowbase + h0]) = *reinterpret_cast<uint64_t*>(lo);
    }
}

// ---------------------------------------------------------------------------
extern "C" void kernel_launch(void* const* d_in, const int* in_sizes, int n_in,
                              void* d_out, int out_size)
{
    const float* x      = (const float*)d_in[0];
    const float* h_prev = (const float*)d_in[1];
    const float* c_prev = (const float*)d_in[2];
    const float* W      = (const float*)d_in[3];
    const float* b      = (const float*)d_in[4];
    const float* gamma  = (const float*)d_in[5];
    const float* beta   = (const float*)d_in[6];
    const float* Wp     = (const float*)d_in[7];
    float* out = (float*)d_out;                       // [out | cell]
    float* out_cell = out + (size_t)BROWS * HDIM;

    cudaFuncSetAttribute(gemm_mma<0>, cudaFuncAttributeMaxDynamicSharedMemorySize, SMEM_DYN);
    cudaFuncSetAttribute(gemm_mma<1>, cudaFuncAttributeMaxDynamicSharedMemorySize, SMEM_DYN);

    __nv_bfloat16 *pAhi, *pAlo, *pWhi, *pWlo, *pShi, *pSlo, *pPhi, *pPlo;
    cudaGetSymbolAddress((void**)&pAhi, g_Ahi);
    cudaGetSymbolAddress((void**)&pAlo, g_Alo);
    cudaGetSymbolAddress((void**)&pWhi, g_Whi);
    cudaGetSymbolAddress((void**)&pWlo, g_Wlo);
    cudaGetSymbolAddress((void**)&pShi, g_Shi);
    cudaGetSymbolAddress((void**)&pSlo, g_Slo);
    cudaGetSymbolAddress((void**)&pPhi, g_Phi);
    cudaGetSymbolAddress((void**)&pPlo, g_Plo);

    // fp32 -> bf16 splits (W gate-interleaved)
    conv_A<<<(BROWS * KDIM1 / 4) / 256, 256>>>(x, h_prev);
    conv_W<true ><<<(NDIM1 * KDIM1 / 4 + 255) / 256, 256>>>(W,  pWhi, pWlo, KDIM1, NDIM1 * KDIM1 / 4);
    conv_W<false><<<(HDIM * HDIM / 4 + 255) / 256, 256>>>(Wp, pPhi, pPlo, HDIM,  HDIM * HDIM / 4);

    // GEMM1: gates + fused bias/activation/cell -> g_cell, g_og
    gemm_mma<0><<<dim3(NDIM1 / 128, BROWS / 128), 256, SMEM_DYN>>>(
        pAhi, pAlo, pWhi, pWlo, b, c_prev, nullptr, KDIM1);

    // LayerNorm + s (bf16 split), warp-per-row
    ln_kernel<<<BROWS / 8, 256>>>(gamma, beta, out_cell);

    // GEMM2: out = s @ Wp^T
    gemm_mma<1><<<dim3(HDIM / 128, BROWS / 128), 256, SMEM_DYN>>>(
        pShi, pSlo, pPhi, pPlo, nullptr, nullptr, out, HDIM);
}